// round 6
// baseline (speedup 1.0000x reference)
#include <cuda_runtime.h>
#include <cmath>
#include <stdint.h>

#define DMAX 256         // max domains supported
#define SMAX 1024        // max superposition dim supported
#define BPDMAX 64        // max blocks-per-domain in reduce
#define RED_THREADS 256

// Scratch (device globals — no allocation allowed)
__device__ float g_part_sum[DMAX][BPDMAX];
__device__ float g_part_sq [DMAX][BPDMAX];
__device__ float g_p[DMAX];
__device__ float g_m[DMAX];
__device__ float g_cr[DMAX][DMAX];
__device__ float g_ci[DMAX][DMAX];
__device__ float g_Tr[DMAX][SMAX];
__device__ float g_Ti[DMAX][SMAX];

// ---------------------------------------------------------------------------
// Kernel 1: per-(domain, chunk) partial sum + sum-of-squares. HBM-bound.
// Grid (bpd, D) x 256 threads. Alignment-safe; extents from in_sizes.
// ---------------------------------------------------------------------------
__global__ __launch_bounds__(RED_THREADS)
void k_reduce(const float* __restrict__ vulns, long long L, int bpd) {
    const int d   = blockIdx.y;
    const int c   = blockIdx.x;
    const int tid = threadIdx.x;
    const float* __restrict__ base = vulns + (long long)d * L;

    const long long span = (L + bpd - 1) / bpd;
    const long long s0   = (long long)c * span;
    long long se = s0 + span; if (se > L) se = L;

    float s1 = 0.f, s2 = 0.f;
    if (s0 < se) {
        // scalar head to 16B alignment
        uintptr_t addr = (uintptr_t)(base + s0);
        long long mis = (long long)(((16u - (unsigned)(addr & 15u)) & 15u) >> 2);
        long long head_end = s0 + mis; if (head_end > se) head_end = se;
        for (long long i = s0 + tid; i < head_end; i += RED_THREADS) {
            float v = base[i]; s1 += v; s2 = fmaf(v, v, s2);
        }
        const long long nvec = (se - head_end) >> 2;
        const float4* __restrict__ vbase = (const float4*)(base + head_end);
        for (long long i = tid; i < nvec; i += RED_THREADS) {
            float4 v = vbase[i];
            s1 += (v.x + v.y) + (v.z + v.w);
            s2 += (v.x * v.x + v.y * v.y) + (v.z * v.z + v.w * v.w);
        }
        for (long long i = head_end + (nvec << 2) + tid; i < se; i += RED_THREADS) {
            float v = base[i]; s1 += v; s2 = fmaf(v, v, s2);
        }
    }

    #pragma unroll
    for (int o = 16; o > 0; o >>= 1) {
        s1 += __shfl_down_sync(0xffffffffu, s1, o);
        s2 += __shfl_down_sync(0xffffffffu, s2, o);
    }
    __shared__ float sh1[RED_THREADS / 32], sh2[RED_THREADS / 32];
    if ((tid & 31) == 0) { sh1[tid >> 5] = s1; sh2[tid >> 5] = s2; }
    __syncthreads();
    if (tid == 0) {
        float t1 = 0.f, t2 = 0.f;
        #pragma unroll
        for (int w = 0; w < RED_THREADS / 32; ++w) { t1 += sh1[w]; t2 += sh2[w]; }
        g_part_sum[d][c] = t1;
        g_part_sq [d][c] = t2;
    }
}

// ---------------------------------------------------------------------------
// Kernel 2: finalize p, m. 1 block x D threads.
// ---------------------------------------------------------------------------
__global__ void k_finalize(int bpd, long long L) {
    const int d = threadIdx.x;
    float s1 = 0.f, s2 = 0.f;
    for (int c = 0; c < bpd; ++c) {
        s1 += g_part_sum[d][c];
        s2 += g_part_sq [d][c];
    }
    g_p[d] = s2;
    g_m[d] = s1 * (1.0f / (float)L);
}

// ---------------------------------------------------------------------------
// Kernel 3: coeff[i][j] for j>i, else 0.
// cos(atan2(mj,mi)) = mi/hyp ; sin = mj/hyp ; amp = sqrt(pi*pj).
// ---------------------------------------------------------------------------
__global__ void k_coeff() {
    const int i = blockIdx.x;
    const int j = threadIdx.x;
    float cr = 0.f, ci = 0.f;
    if (j > i) {
        const float mi = g_m[i], mj = g_m[j];
        const float amp = sqrtf(g_p[i] * g_p[j]);
        const float inv = rsqrtf(mi * mi + mj * mj);
        cr = amp * mi * inv;
        ci = amp * mj * inv;
    }
    g_cr[i][j] = cr;
    g_ci[i][j] = ci;
}

// ---------------------------------------------------------------------------
// Kernel 4: T = coeff @ E  (complex [D,S]); triangular: j in (i, D).
// ---------------------------------------------------------------------------
__global__ __launch_bounds__(128)
void k_T(const float* __restrict__ embed, int D, int S) {
    const int i = blockIdx.y;
    const int s = blockIdx.x * 128 + threadIdx.x;

    __shared__ float scr[DMAX], sci[DMAX];
    for (int j = threadIdx.x; j < D; j += 128) {
        scr[j] = g_cr[i][j];
        sci[j] = g_ci[i][j];
    }
    __syncthreads();
    if (s >= S) return;

    float ar = 0.f, ai = 0.f;
    for (int j = i + 1; j < D; ++j) {
        const float e = embed[(long long)j * S + s];   // coalesced
        ar = fmaf(scr[j], e, ar);
        ai = fmaf(sci[j], e, ai);
    }
    g_Tr[i][s] = ar;
    g_Ti[i][s] = ai;
}

// ---------------------------------------------------------------------------
// Kernel 5: out[a][b] = sum_i E[i][a] * T[i][b]  (E^T @ T).
// mode 0: output buffer is S*S float32 (REAL PART ONLY — complex64 coerced
//         to float32 by the harness). Writes exactly out_size floats.
// mode 1: output buffer is S*S interleaved complex64 (2*S*S floats).
// Both modes write exactly the buffer size — no OOB possible.
// ---------------------------------------------------------------------------
__global__ __launch_bounds__(256)
void k_out(const float* __restrict__ embed, float* __restrict__ out,
           int D, int S, int mode) {
    const int tx = threadIdx.x;
    const int ty = threadIdx.y;
    const int b0 = blockIdx.x * 16;
    const int a0 = blockIdx.y * 16;

    __shared__ float Es [16][17];
    __shared__ float Trs[16][17];
    __shared__ float Tis[16][17];

    float ar = 0.f, ai = 0.f;
    for (int k0 = 0; k0 < D; k0 += 16) {
        const int k = k0 + ty;
        const bool kv = (k < D);
        Es [ty][tx] = (kv && a0 + tx < S) ? embed[(long long)k * S + a0 + tx] : 0.f;
        Trs[ty][tx] = (kv && b0 + tx < S) ? g_Tr[k][b0 + tx] : 0.f;
        Tis[ty][tx] = (kv && b0 + tx < S) ? g_Ti[k][b0 + tx] : 0.f;
        __syncthreads();
        #pragma unroll
        for (int kk = 0; kk < 16; ++kk) {
            const float e = Es[kk][ty];
            ar = fmaf(e, Trs[kk][tx], ar);
            ai = fmaf(e, Tis[kk][tx], ai);
        }
        __syncthreads();
    }
    const int a = a0 + ty, b = b0 + tx;
    if (a < S && b < S) {
        const long long idx = (long long)a * S + b;
        if (mode == 0) {
            out[idx] = ar;                       // real part, S*S floats total
        } else {
            out[2 * idx]     = ar;               // interleaved complex64
            out[2 * idx + 1] = ai;
        }
    }
}

// ---------------------------------------------------------------------------
static long long isqrt_exact(long long x) {
    if (x <= 0) return -1;
    long long r = (long long)llround(sqrt((double)x));
    for (long long c = r - 2; c <= r + 2; ++c)
        if (c > 0 && c * c == x) return c;
    return -1;
}

extern "C" void kernel_launch(void* const* d_in, const int* in_sizes, int n_in,
                              void* d_out, int out_size) {
    if (n_in < 2) return;

    // Decode output mode + S:
    //  out_size == S*S      -> float32 real-part output (complex coerced)
    //  out_size == 2*S*S    -> interleaved complex64 output
    int mode = 0;
    long long S_ll = isqrt_exact((long long)out_size);
    if (S_ll < 0 && (out_size % 2) == 0) {
        S_ll = isqrt_exact((long long)out_size / 2);
        mode = 1;
    }
    if (S_ll < 1) S_ll = 1;
    int S = (int)S_ll;
    if (S > SMAX) S = SMAX;

    // Identify inputs by size: embed is the smaller tensor [D,S], vulns [D,L].
    long long sz0 = in_sizes[0], sz1 = in_sizes[1];
    const float* vulns; const float* embed;
    long long vsz, esz;
    if (sz0 >= sz1) { vulns = (const float*)d_in[0]; vsz = sz0;
                      embed = (const float*)d_in[1]; esz = sz1; }
    else            { vulns = (const float*)d_in[1]; vsz = sz1;
                      embed = (const float*)d_in[0]; esz = sz0; }

    int D = (int)(esz / S);            // D*S <= esz
    if (D < 1) D = 1;
    if (D > DMAX) D = DMAX;
    long long L = vsz / D;             // D*L <= vsz
    if (L < 1) L = 1;

    int bpd = (2048 + D - 1) / D;
    if (bpd < 1) bpd = 1;
    if (bpd > BPDMAX) bpd = BPDMAX;

    float* out = (float*)d_out;

    k_reduce  <<<dim3(bpd, D), RED_THREADS>>>(vulns, L, bpd);
    k_finalize<<<1, D>>>(bpd, L);
    k_coeff   <<<D, D>>>();
    k_T       <<<dim3((S + 127) / 128, D), 128>>>(embed, D, S);
    k_out     <<<dim3((S + 15) / 16, (S + 15) / 16), dim3(16, 16)>>>(embed, out, D, S, mode);
}

// round 7
// speedup vs baseline: 1.0019x; 1.0019x over previous
#include <cuda_runtime.h>
#include <cmath>
#include <stdint.h>

#define DMAX 256         // max domains supported
#define SMAX 1024        // max superposition dim supported
#define BPDMAX 64        // max blocks-per-domain in reduce
#define RED_THREADS 256

// Scratch (device globals — no allocation allowed)
__device__ float g_part_sum[DMAX][BPDMAX];
__device__ float g_part_sq [DMAX][BPDMAX];
__device__ float g_cr[DMAX][DMAX];
__device__ float g_ci[DMAX][DMAX];
__device__ float g_Tr[DMAX][SMAX];
__device__ float g_Ti[DMAX][SMAX];

// ---------------------------------------------------------------------------
// Kernel 1: per-(domain, chunk) partial sum + sum-of-squares. HBM streaming.
// Grid sized to ~one full wave (bpd*D ~ 1152 CTAs @ 8/SM). 4x-batched float4
// loads for MLP. Alignment-safe head/tail. int indices (in_sizes is int).
// ---------------------------------------------------------------------------
__global__ __launch_bounds__(RED_THREADS)
void k_reduce(const float* __restrict__ vulns, int L, int bpd) {
    const int d   = blockIdx.y;
    const int c   = blockIdx.x;
    const int tid = threadIdx.x;
    const float* __restrict__ base = vulns + (size_t)d * (size_t)L;

    const int span = (L + bpd - 1) / bpd;
    const int s0   = c * span;
    int se = s0 + span; if (se > L) se = L;

    float s1a = 0.f, s1b = 0.f, s2a = 0.f, s2b = 0.f;
    if (s0 < se) {
        // scalar head to 16B alignment
        uintptr_t addr = (uintptr_t)(base + s0);
        int mis = (int)(((16u - (unsigned)(addr & 15u)) & 15u) >> 2);
        int head_end = s0 + mis; if (head_end > se) head_end = se;
        for (int i = s0 + tid; i < head_end; i += RED_THREADS) {
            float v = base[i]; s1a += v; s2a = fmaf(v, v, s2a);
        }
        const int nvec = (se - head_end) >> 2;
        const float4* __restrict__ vbase = (const float4*)(base + head_end);

        int i = tid;
        // 4 independent loads per iteration -> MLP>=4 per warp
        for (; i + 3 * RED_THREADS < nvec; i += 4 * RED_THREADS) {
            float4 v0 = vbase[i];
            float4 v1 = vbase[i +     RED_THREADS];
            float4 v2 = vbase[i + 2 * RED_THREADS];
            float4 v3 = vbase[i + 3 * RED_THREADS];
            s1a += (v0.x + v0.y) + (v0.z + v0.w);
            s1b += (v1.x + v1.y) + (v1.z + v1.w);
            s1a += (v2.x + v2.y) + (v2.z + v2.w);
            s1b += (v3.x + v3.y) + (v3.z + v3.w);
            s2a += (v0.x * v0.x + v0.y * v0.y) + (v0.z * v0.z + v0.w * v0.w);
            s2b += (v1.x * v1.x + v1.y * v1.y) + (v1.z * v1.z + v1.w * v1.w);
            s2a += (v2.x * v2.x + v2.y * v2.y) + (v2.z * v2.z + v2.w * v2.w);
            s2b += (v3.x * v3.x + v3.y * v3.y) + (v3.z * v3.z + v3.w * v3.w);
        }
        for (; i < nvec; i += RED_THREADS) {
            float4 v = vbase[i];
            s1a += (v.x + v.y) + (v.z + v.w);
            s2a += (v.x * v.x + v.y * v.y) + (v.z * v.z + v.w * v.w);
        }
        // scalar tail
        for (int t = head_end + (nvec << 2) + tid; t < se; t += RED_THREADS) {
            float v = base[t]; s1a += v; s2a = fmaf(v, v, s2a);
        }
    }
    float s1 = s1a + s1b;
    float s2 = s2a + s2b;

    #pragma unroll
    for (int o = 16; o > 0; o >>= 1) {
        s1 += __shfl_down_sync(0xffffffffu, s1, o);
        s2 += __shfl_down_sync(0xffffffffu, s2, o);
    }
    __shared__ float sh1[RED_THREADS / 32], sh2[RED_THREADS / 32];
    if ((tid & 31) == 0) { sh1[tid >> 5] = s1; sh2[tid >> 5] = s2; }
    __syncthreads();
    if (tid == 0) {
        float t1 = 0.f, t2 = 0.f;
        #pragma unroll
        for (int w = 0; w < RED_THREADS / 32; ++w) { t1 += sh1[w]; t2 += sh2[w]; }
        g_part_sum[d][c] = t1;
        g_part_sq [d][c] = t2;
    }
}

// ---------------------------------------------------------------------------
// Kernel 2: fused finalize + coeff. Block i, thread j.
// Every block redundantly reduces partials (cheap: D*bpd adds) into smem,
// then coeff[i][j] = amp*cos / amp*sin via algebraic atan2 identity.
// ---------------------------------------------------------------------------
__global__ void k_coeff(int bpd, float invL, int withImag) {
    const int i = blockIdx.x;
    const int j = threadIdx.x;
    __shared__ float sm[DMAX], sp[DMAX];
    float s1 = 0.f, s2 = 0.f;
    for (int c = 0; c < bpd; ++c) {
        s1 += g_part_sum[j][c];
        s2 += g_part_sq [j][c];
    }
    sm[j] = s1 * invL;
    sp[j] = s2;
    __syncthreads();

    float cr = 0.f, ci = 0.f;
    if (j > i) {
        const float mi = sm[i], mj = sm[j];
        const float amp = sqrtf(sp[i] * sp[j]);
        const float inv = rsqrtf(mi * mi + mj * mj);
        cr = amp * mi * inv;
        ci = amp * mj * inv;
    }
    g_cr[i][j] = cr;
    if (withImag) g_ci[i][j] = ci;
}

// ---------------------------------------------------------------------------
// Kernel 3: Tr = cr @ E (real only; + Ti if withImag). One block per row i,
// 256 threads, float2 embed loads. Triangular: j in (i, D).
// ---------------------------------------------------------------------------
__global__ __launch_bounds__(256)
void k_T(const float* __restrict__ embed, int D, int S, int withImag) {
    const int i   = blockIdx.x;
    const int tid = threadIdx.x;

    __shared__ float scr[DMAX], sci[DMAX];
    for (int j = tid; j < D; j += 256) {
        scr[j] = g_cr[i][j];
        sci[j] = withImag ? g_ci[i][j] : 0.f;
    }
    __syncthreads();

    const int halfS = S >> 1;
    const float2* __restrict__ e2 = (const float2*)embed;   // S even in practice

    for (int s2i = tid; s2i < halfS; s2i += 256) {
        float2 ar = make_float2(0.f, 0.f);
        float2 ai = make_float2(0.f, 0.f);
        #pragma unroll 4
        for (int j = i + 1; j < D; ++j) {
            const float2 e = e2[(size_t)j * halfS + s2i];
            const float c = scr[j];
            ar.x = fmaf(c, e.x, ar.x);
            ar.y = fmaf(c, e.y, ar.y);
            if (withImag) {
                const float ic = sci[j];
                ai.x = fmaf(ic, e.x, ai.x);
                ai.y = fmaf(ic, e.y, ai.y);
            }
        }
        ((float2*)g_Tr[i])[s2i] = ar;
        if (withImag) ((float2*)g_Ti[i])[s2i] = ai;
    }
    // odd-S scalar tail (not hit for S=512)
    if ((S & 1) && tid == 0) {
        const int s = S - 1;
        float ar = 0.f, ai = 0.f;
        for (int j = i + 1; j < D; ++j) {
            ar = fmaf(scr[j], embed[(size_t)j * S + s], ar);
            ai = fmaf(sci[j], embed[(size_t)j * S + s], ai);
        }
        g_Tr[i][s] = ar;
        if (withImag) g_Ti[i][s] = ai;
    }
}

// ---------------------------------------------------------------------------
// Kernel 4: out[a][b] = sum_k E[k][a] * Tr[k][b]  (E^T @ Tr), REAL output.
// 32x32 tiles, 16x16 threads, 2x2 register blocking. Writes exactly S*S
// floats (= out_size in mode 0).
// ---------------------------------------------------------------------------
__global__ __launch_bounds__(256)
void k_out_real(const float* __restrict__ embed, float* __restrict__ out,
                int D, int S) {
    const int tx = threadIdx.x;             // 0..15
    const int ty = threadIdx.y;             // 0..15
    const int tid = ty * 16 + tx;
    const int b0 = blockIdx.x * 32;
    const int a0 = blockIdx.y * 32;

    __shared__ float Es [16][33];
    __shared__ float Trs[16][33];

    float r00 = 0.f, r01 = 0.f, r10 = 0.f, r11 = 0.f;

    for (int k0 = 0; k0 < D; k0 += 16) {
        // cooperative load: 16x32 tiles, 2 elems/thread each
        #pragma unroll
        for (int u = 0; u < 2; ++u) {
            const int idx = tid + u * 256;
            const int kk = idx >> 5, cc = idx & 31;
            const int k = k0 + kk;
            Es [kk][cc] = (k < D && a0 + cc < S) ? embed[(size_t)k * S + a0 + cc] : 0.f;
            Trs[kk][cc] = (k < D && b0 + cc < S) ? g_Tr[k][b0 + cc] : 0.f;
        }
        __syncthreads();
        #pragma unroll
        for (int kk = 0; kk < 16; ++kk) {
            const float e0 = Es[kk][ty];
            const float e1 = Es[kk][ty + 16];
            const float t0 = Trs[kk][tx];
            const float t1 = Trs[kk][tx + 16];
            r00 = fmaf(e0, t0, r00);
            r01 = fmaf(e0, t1, r01);
            r10 = fmaf(e1, t0, r10);
            r11 = fmaf(e1, t1, r11);
        }
        __syncthreads();
    }
    const int a = a0 + ty, b = b0 + tx;
    if (a < S && b < S)           out[(size_t)a * S + b]               = r00;
    if (a < S && b + 16 < S)      out[(size_t)a * S + b + 16]          = r01;
    if (a + 16 < S && b < S)      out[(size_t)(a + 16) * S + b]        = r10;
    if (a + 16 < S && b + 16 < S) out[(size_t)(a + 16) * S + b + 16]   = r11;
}

// ---------------------------------------------------------------------------
// Kernel 4b: interleaved complex64 output (mode 1 fallback; not the measured
// reality but kept write-exact for safety).
// ---------------------------------------------------------------------------
__global__ __launch_bounds__(256)
void k_out_cplx(const float* __restrict__ embed, float2* __restrict__ out,
                int D, int S) {
    const int tx = threadIdx.x, ty = threadIdx.y;
    const int b0 = blockIdx.x * 16, a0 = blockIdx.y * 16;
    __shared__ float Es[16][17], Trs[16][17], Tis[16][17];
    float ar = 0.f, ai = 0.f;
    for (int k0 = 0; k0 < D; k0 += 16) {
        const int k = k0 + ty;
        const bool kv = (k < D);
        Es [ty][tx] = (kv && a0 + tx < S) ? embed[(size_t)k * S + a0 + tx] : 0.f;
        Trs[ty][tx] = (kv && b0 + tx < S) ? g_Tr[k][b0 + tx] : 0.f;
        Tis[ty][tx] = (kv && b0 + tx < S) ? g_Ti[k][b0 + tx] : 0.f;
        __syncthreads();
        #pragma unroll
        for (int kk = 0; kk < 16; ++kk) {
            const float e = Es[kk][ty];
            ar = fmaf(e, Trs[kk][tx], ar);
            ai = fmaf(e, Tis[kk][tx], ai);
        }
        __syncthreads();
    }
    const int a = a0 + ty, b = b0 + tx;
    if (a < S && b < S) out[(size_t)a * S + b] = make_float2(ar, ai);
}

// ---------------------------------------------------------------------------
static long long isqrt_exact(long long x) {
    if (x <= 0) return -1;
    long long r = (long long)llround(sqrt((double)x));
    for (long long c = r - 2; c <= r + 2; ++c)
        if (c > 0 && c * c == x) return c;
    return -1;
}

extern "C" void kernel_launch(void* const* d_in, const int* in_sizes, int n_in,
                              void* d_out, int out_size) {
    if (n_in < 2) return;

    // Decode output mode + S:
    //  out_size == S*S    -> float32 real-part output (confirmed reality)
    //  out_size == 2*S*S  -> interleaved complex64 fallback
    int mode = 0;
    long long S_ll = isqrt_exact((long long)out_size);
    if (S_ll < 0 && (out_size % 2) == 0) {
        S_ll = isqrt_exact((long long)out_size / 2);
        mode = 1;
    }
    if (S_ll < 1) S_ll = 1;
    int S = (int)S_ll;
    if (S > SMAX) S = SMAX;

    // Identify inputs by size: embed is the smaller tensor [D,S], vulns [D,L].
    long long sz0 = in_sizes[0], sz1 = in_sizes[1];
    const float* vulns; const float* embed;
    long long vsz, esz;
    if (sz0 >= sz1) { vulns = (const float*)d_in[0]; vsz = sz0;
                      embed = (const float*)d_in[1]; esz = sz1; }
    else            { vulns = (const float*)d_in[1]; vsz = sz1;
                      embed = (const float*)d_in[0]; esz = sz0; }

    int D = (int)(esz / S);
    if (D < 1) D = 1;
    if (D > DMAX) D = DMAX;
    long long L_ll = vsz / D;
    if (L_ll < 1) L_ll = 1;
    int L = (int)L_ll;                 // in_sizes is int -> fits

    // One full wave: ~148 SMs * 8 CTAs (256 thr) = 1184 slots.
    int bpd = (1184 + D - 1) / D;      // D=128 -> 9 -> 1152 CTAs
    if (bpd < 1) bpd = 1;
    if (bpd > BPDMAX) bpd = BPDMAX;

    k_reduce<<<dim3(bpd, D), RED_THREADS>>>(vulns, L, bpd);
    k_coeff <<<D, D>>>(bpd, 1.0f / (float)L, mode);
    k_T     <<<D, 256>>>(embed, D, S, mode);
    if (mode == 0) {
        k_out_real<<<dim3((S + 31) / 32, (S + 31) / 32), dim3(16, 16)>>>(
            embed, (float*)d_out, D, S);
    } else {
        k_out_cplx<<<dim3((S + 15) / 16, (S + 15) / 16), dim3(16, 16)>>>(
            embed, (float2*)d_out, D, S);
    }
}

// round 8
// speedup vs baseline: 1.0619x; 1.0599x over previous
#include <cuda_runtime.h>
#include <cmath>
#include <stdint.h>

#define DMAX 256         // max domains supported
#define SMAX 1024        // max superposition dim supported
#define BPDMAX 64        // max blocks-per-domain in reduce
#define RED_THREADS 256
#define KC 64            // K-chunk for k_out_real

// Scratch (device globals — no allocation allowed)
__device__ float g_part_sum[DMAX][BPDMAX];
__device__ float g_part_sq [DMAX][BPDMAX];
__device__ float g_cr[DMAX][DMAX];
__device__ float g_ci[DMAX][DMAX];
__device__ float g_Tr[DMAX][SMAX];
__device__ float g_Ti[DMAX][SMAX];

// ---------------------------------------------------------------------------
// Kernel 1: per-(domain, chunk) partial sum + sum-of-squares. HBM streaming
// at the achieved-BW ceiling (~5.5-5.8 TB/s — grid-shape insensitive, R6=R7).
// __ldcs: read-once stream, evict-first. Alignment-safe head/tail.
// ---------------------------------------------------------------------------
__global__ __launch_bounds__(RED_THREADS)
void k_reduce(const float* __restrict__ vulns, int L, int bpd) {
    const int d   = blockIdx.y;
    const int c   = blockIdx.x;
    const int tid = threadIdx.x;
    const float* __restrict__ base = vulns + (size_t)d * (size_t)L;

    const int span = (L + bpd - 1) / bpd;
    const int s0   = c * span;
    int se = s0 + span; if (se > L) se = L;

    float s1a = 0.f, s1b = 0.f, s2a = 0.f, s2b = 0.f;
    if (s0 < se) {
        uintptr_t addr = (uintptr_t)(base + s0);
        int mis = (int)(((16u - (unsigned)(addr & 15u)) & 15u) >> 2);
        int head_end = s0 + mis; if (head_end > se) head_end = se;
        for (int i = s0 + tid; i < head_end; i += RED_THREADS) {
            float v = base[i]; s1a += v; s2a = fmaf(v, v, s2a);
        }
        const int nvec = (se - head_end) >> 2;
        const float4* __restrict__ vbase = (const float4*)(base + head_end);

        int i = tid;
        for (; i + 3 * RED_THREADS < nvec; i += 4 * RED_THREADS) {
            float4 v0 = __ldcs(vbase + i);
            float4 v1 = __ldcs(vbase + i +     RED_THREADS);
            float4 v2 = __ldcs(vbase + i + 2 * RED_THREADS);
            float4 v3 = __ldcs(vbase + i + 3 * RED_THREADS);
            s1a += (v0.x + v0.y) + (v0.z + v0.w);
            s1b += (v1.x + v1.y) + (v1.z + v1.w);
            s1a += (v2.x + v2.y) + (v2.z + v2.w);
            s1b += (v3.x + v3.y) + (v3.z + v3.w);
            s2a += (v0.x * v0.x + v0.y * v0.y) + (v0.z * v0.z + v0.w * v0.w);
            s2b += (v1.x * v1.x + v1.y * v1.y) + (v1.z * v1.z + v1.w * v1.w);
            s2a += (v2.x * v2.x + v2.y * v2.y) + (v2.z * v2.z + v2.w * v2.w);
            s2b += (v3.x * v3.x + v3.y * v3.y) + (v3.z * v3.z + v3.w * v3.w);
        }
        for (; i < nvec; i += RED_THREADS) {
            float4 v = __ldcs(vbase + i);
            s1a += (v.x + v.y) + (v.z + v.w);
            s2a += (v.x * v.x + v.y * v.y) + (v.z * v.z + v.w * v.w);
        }
        for (int t = head_end + (nvec << 2) + tid; t < se; t += RED_THREADS) {
            float v = base[t]; s1a += v; s2a = fmaf(v, v, s2a);
        }
    }
    float s1 = s1a + s1b;
    float s2 = s2a + s2b;

    #pragma unroll
    for (int o = 16; o > 0; o >>= 1) {
        s1 += __shfl_down_sync(0xffffffffu, s1, o);
        s2 += __shfl_down_sync(0xffffffffu, s2, o);
    }
    __shared__ float sh1[RED_THREADS / 32], sh2[RED_THREADS / 32];
    if ((tid & 31) == 0) { sh1[tid >> 5] = s1; sh2[tid >> 5] = s2; }
    __syncthreads();
    if (tid == 0) {
        float t1 = 0.f, t2 = 0.f;
        #pragma unroll
        for (int w = 0; w < RED_THREADS / 32; ++w) { t1 += sh1[w]; t2 += sh2[w]; }
        g_part_sum[d][c] = t1;
        g_part_sq [d][c] = t2;
    }
}

// ---------------------------------------------------------------------------
// Kernel 2: FUSED finalize + coeff + T.
// Block (x=chunk of S/2, y=row i), 128 threads. Each block redundantly
// reduces the tiny partial arrays (L2-hot) -> m,p -> coeff row i in smem,
// then Tr[i] (and Ti[i] if withImag) for its float2-chunk.
// coeff identity: cos(atan2(mj,mi))=mi/hyp, sin=mj/hyp, amp=sqrt(pi*pj).
// ---------------------------------------------------------------------------
__global__ __launch_bounds__(128)
void k_T(const float* __restrict__ embed, int D, int S,
         int bpd, float invL, int withImag) {
    const int i   = blockIdx.y;
    const int tid = threadIdx.x;

    __shared__ float sm[DMAX], sp[DMAX];
    __shared__ float scr[DMAX], sci[DMAX];

    for (int j = tid; j < D; j += 128) {
        float s1 = 0.f, s2 = 0.f;
        for (int c = 0; c < bpd; ++c) {
            s1 += g_part_sum[j][c];
            s2 += g_part_sq [j][c];
        }
        sm[j] = s1 * invL;
        sp[j] = s2;
    }
    __syncthreads();
    for (int j = tid; j < D; j += 128) {
        float cr = 0.f, ci = 0.f;
        if (j > i) {
            const float mi = sm[i], mj = sm[j];
            const float amp = sqrtf(sp[i] * sp[j]);
            const float inv = rsqrtf(mi * mi + mj * mj);
            cr = amp * mi * inv;
            ci = amp * mj * inv;
        }
        scr[j] = cr;
        sci[j] = ci;
    }
    __syncthreads();
    if (withImag) {           // persist coeff for the complex fallback path
        for (int j = tid; j < D; j += 128) {
            g_cr[i][j] = scr[j];
            g_ci[i][j] = sci[j];
        }
    }

    const int halfS = S >> 1;
    const int s2i = blockIdx.x * 128 + tid;
    if (s2i < halfS) {
        const float2* __restrict__ e2 = (const float2*)embed;
        float2 ar = make_float2(0.f, 0.f);
        float2 ai = make_float2(0.f, 0.f);
        #pragma unroll 4
        for (int j = i + 1; j < D; ++j) {
            const float2 e = e2[(size_t)j * halfS + s2i];
            const float c = scr[j];
            ar.x = fmaf(c, e.x, ar.x);
            ar.y = fmaf(c, e.y, ar.y);
            if (withImag) {
                const float ic = sci[j];
                ai.x = fmaf(ic, e.x, ai.x);
                ai.y = fmaf(ic, e.y, ai.y);
            }
        }
        ((float2*)g_Tr[i])[s2i] = ar;
        if (withImag) ((float2*)g_Ti[i])[s2i] = ai;
    }
    // odd-S scalar tail
    if ((S & 1) && blockIdx.x == 0 && tid == 0) {
        const int s = S - 1;
        float ar = 0.f, ai = 0.f;
        for (int j = i + 1; j < D; ++j) {
            ar = fmaf(scr[j], embed[(size_t)j * S + s], ar);
            ai = fmaf(sci[j], embed[(size_t)j * S + s], ai);
        }
        g_Tr[i][s] = ar;
        if (withImag) g_Ti[i][s] = ai;
    }
}

// ---------------------------------------------------------------------------
// Kernel 3 (fast path, S%4==0): out = E^T @ Tr, REAL output.
// 32(a) x 64(b) tiles -> (S/64)*(S/32) = 128 blocks @ S=512 = ONE wave.
// K chunked by KC=64 into smem: only 2*ceil(D/KC) barriers per block.
// 2x4 register blocking; float4 global+smem I/O; E reads broadcast,
// Tr LDS.128 conflict-free.
// ---------------------------------------------------------------------------
__global__ __launch_bounds__(256)
void k_out_fast(const float* __restrict__ embed, float* __restrict__ out,
                int D, int S) {
    const int tid = threadIdx.x;
    const int tb  = tid & 15;          // b-group 0..15 (4 cols each)
    const int ta  = tid >> 4;          // a 0..15 (2 rows: ta, ta+16)
    const int b0  = blockIdx.x * 64;
    const int a0  = blockIdx.y * 32;

    __shared__ float Es [KC][32];
    __shared__ float Trs[KC][64];

    float a00 = 0.f, a01 = 0.f, a02 = 0.f, a03 = 0.f;
    float a10 = 0.f, a11 = 0.f, a12 = 0.f, a13 = 0.f;

    for (int k0 = 0; k0 < D; k0 += KC) {
        // load E tile: KC x 32 floats = 512 float4, 2 per thread
        #pragma unroll
        for (int u = 0; u < 2; ++u) {
            const int e = tid + u * 256;         // 0..511
            const int kk = e >> 3, cc = (e & 7) << 2;
            const int k = k0 + kk;
            float4 v = make_float4(0.f, 0.f, 0.f, 0.f);
            if (k < D && a0 + cc + 3 < S)
                v = *(const float4*)&embed[(size_t)k * S + a0 + cc];
            *(float4*)&Es[kk][cc] = v;
        }
        // load Tr tile: KC x 64 floats = 1024 float4, 4 per thread
        #pragma unroll
        for (int u = 0; u < 4; ++u) {
            const int e = tid + u * 256;         // 0..1023
            const int kk = e >> 4, cc = (e & 15) << 2;
            const int k = k0 + kk;
            float4 v = make_float4(0.f, 0.f, 0.f, 0.f);
            if (k < D && b0 + cc + 3 < S)
                v = *(const float4*)&g_Tr[k][b0 + cc];
            *(float4*)&Trs[kk][cc] = v;
        }
        __syncthreads();
        #pragma unroll 8
        for (int kk = 0; kk < KC; ++kk) {
            const float e0 = Es[kk][ta];
            const float e1 = Es[kk][ta + 16];
            const float4 t = *(const float4*)&Trs[kk][tb << 2];
            a00 = fmaf(e0, t.x, a00); a01 = fmaf(e0, t.y, a01);
            a02 = fmaf(e0, t.z, a02); a03 = fmaf(e0, t.w, a03);
            a10 = fmaf(e1, t.x, a10); a11 = fmaf(e1, t.y, a11);
            a12 = fmaf(e1, t.z, a12); a13 = fmaf(e1, t.w, a13);
        }
        __syncthreads();
    }
    const int b = b0 + (tb << 2);
    const int aA = a0 + ta, aB = a0 + ta + 16;
    if (aA < S && b + 3 < S)
        *(float4*)&out[(size_t)aA * S + b] = make_float4(a00, a01, a02, a03);
    if (aB < S && b + 3 < S)
        *(float4*)&out[(size_t)aB * S + b] = make_float4(a10, a11, a12, a13);
}

// ---------------------------------------------------------------------------
// Kernel 3 (generic real fallback, any S): 16x16 tiles.
// ---------------------------------------------------------------------------
__global__ __launch_bounds__(256)
void k_out_gen(const float* __restrict__ embed, float* __restrict__ out,
               int D, int S) {
    const int tx = threadIdx.x, ty = threadIdx.y;
    const int b0 = blockIdx.x * 16, a0 = blockIdx.y * 16;
    __shared__ float Es[16][17], Trs[16][17];
    float ar = 0.f;
    for (int k0 = 0; k0 < D; k0 += 16) {
        const int k = k0 + ty;
        const bool kv = (k < D);
        Es [ty][tx] = (kv && a0 + tx < S) ? embed[(size_t)k * S + a0 + tx] : 0.f;
        Trs[ty][tx] = (kv && b0 + tx < S) ? g_Tr[k][b0 + tx] : 0.f;
        __syncthreads();
        #pragma unroll
        for (int kk = 0; kk < 16; ++kk)
            ar = fmaf(Es[kk][ty], Trs[kk][tx], ar);
        __syncthreads();
    }
    const int a = a0 + ty, b = b0 + tx;
    if (a < S && b < S) out[(size_t)a * S + b] = ar;
}

// ---------------------------------------------------------------------------
// Kernel 3b: interleaved complex64 output (mode-1 fallback).
// ---------------------------------------------------------------------------
__global__ __launch_bounds__(256)
void k_out_cplx(const float* __restrict__ embed, float2* __restrict__ out,
                int D, int S) {
    const int tx = threadIdx.x, ty = threadIdx.y;
    const int b0 = blockIdx.x * 16, a0 = blockIdx.y * 16;
    __shared__ float Es[16][17], Trs[16][17], Tis[16][17];
    float ar = 0.f, ai = 0.f;
    for (int k0 = 0; k0 < D; k0 += 16) {
        const int k = k0 + ty;
        const bool kv = (k < D);
        Es [ty][tx] = (kv && a0 + tx < S) ? embed[(size_t)k * S + a0 + tx] : 0.f;
        Trs[ty][tx] = (kv && b0 + tx < S) ? g_Tr[k][b0 + tx] : 0.f;
        Tis[ty][tx] = (kv && b0 + tx < S) ? g_Ti[k][b0 + tx] : 0.f;
        __syncthreads();
        #pragma unroll
        for (int kk = 0; kk < 16; ++kk) {
            const float e = Es[kk][ty];
            ar = fmaf(e, Trs[kk][tx], ar);
            ai = fmaf(e, Tis[kk][tx], ai);
        }
        __syncthreads();
    }
    const int a = a0 + ty, b = b0 + tx;
    if (a < S && b < S) out[(size_t)a * S + b] = make_float2(ar, ai);
}

// ---------------------------------------------------------------------------
static long long isqrt_exact(long long x) {
    if (x <= 0) return -1;
    long long r = (long long)llround(sqrt((double)x));
    for (long long c = r - 2; c <= r + 2; ++c)
        if (c > 0 && c * c == x) return c;
    return -1;
}

extern "C" void kernel_launch(void* const* d_in, const int* in_sizes, int n_in,
                              void* d_out, int out_size) {
    if (n_in < 2) return;

    // Decode output mode + S:
    //  out_size == S*S    -> float32 real-part output (confirmed)
    //  out_size == 2*S*S  -> interleaved complex64 fallback
    int mode = 0;
    long long S_ll = isqrt_exact((long long)out_size);
    if (S_ll < 0 && (out_size % 2) == 0) {
        S_ll = isqrt_exact((long long)out_size / 2);
        mode = 1;
    }
    if (S_ll < 1) S_ll = 1;
    int S = (int)S_ll;
    if (S > SMAX) S = SMAX;

    // Identify inputs by size: embed is the smaller tensor [D,S], vulns [D,L].
    long long sz0 = in_sizes[0], sz1 = in_sizes[1];
    const float* vulns; const float* embed;
    long long vsz, esz;
    if (sz0 >= sz1) { vulns = (const float*)d_in[0]; vsz = sz0;
                      embed = (const float*)d_in[1]; esz = sz1; }
    else            { vulns = (const float*)d_in[1]; vsz = sz1;
                      embed = (const float*)d_in[0]; esz = sz0; }

    int D = (int)(esz / S);
    if (D < 1) D = 1;
    if (D > DMAX) D = DMAX;
    long long L_ll = vsz / D;
    if (L_ll < 1) L_ll = 1;
    int L = (int)L_ll;

    int bpd = (1184 + D - 1) / D;      // ~one full wave
    if (bpd < 1) bpd = 1;
    if (bpd > BPDMAX) bpd = BPDMAX;

    k_reduce<<<dim3(bpd, D), RED_THREADS>>>(vulns, L, bpd);

    const int halfS = S >> 1;
    const int tchunks = (halfS + 127) / 128 > 0 ? (halfS + 127) / 128 : 1;
    k_T<<<dim3(tchunks, D), 128>>>(embed, D, S, bpd, 1.0f / (float)L, mode);

    if (mode == 0) {
        bool fast = ((S & 3) == 0) && (((uintptr_t)embed & 15u) == 0) &&
                    (((uintptr_t)d_out & 15u) == 0);
        if (fast) {
            k_out_fast<<<dim3((S + 63) / 64, (S + 31) / 32), 256>>>(
                embed, (float*)d_out, D, S);
        } else {
            k_out_gen<<<dim3((S + 15) / 16, (S + 15) / 16), dim3(16, 16)>>>(
                embed, (float*)d_out, D, S);
        }
    } else {
        k_out_cplx<<<dim3((S + 15) / 16, (S + 15) / 16), dim3(16, 16)>>>(
            embed, (float2*)d_out, D, S);
    }
}

// round 9
// speedup vs baseline: 1.2405x; 1.1682x over previous
#include <cuda_runtime.h>
#include <cmath>
#include <stdint.h>

#define DMAX 256         // max domains supported
#define SMAX 1024        // max superposition dim supported
#define BPDMAX 64        // max blocks-per-domain in reduce
#define RED_THREADS 256
#define KC 64            // K-chunk for k_out_fast

// Scratch (device globals — no allocation allowed)
__device__ float g_part_sum[DMAX][BPDMAX];
__device__ float g_part_sq [DMAX][BPDMAX];
__device__ float g_cr[DMAX][DMAX];
__device__ float g_ci[DMAX][DMAX];
__device__ float g_Tr[DMAX][SMAX];
__device__ float g_Ti[DMAX][SMAX];

// ---------------------------------------------------------------------------
// Kernel 1: per-(domain, chunk) partial sum + sum-of-squares. HBM streaming.
// __launch_bounds__(256, 4): allow ~64 regs so EIGHT LDG.128 can be truly
// front-batched per thread (R8 showed regs=32 silently serialized the batch:
// DRAM 76.7% duty, issue 16%). 40 warps/SM x 8 in-flight >> latency product.
// ---------------------------------------------------------------------------
__global__ __launch_bounds__(RED_THREADS, 4)
void k_reduce(const float* __restrict__ vulns, int L, int bpd) {
    const int d   = blockIdx.y;
    const int c   = blockIdx.x;
    const int tid = threadIdx.x;
    const float* __restrict__ base = vulns + (size_t)d * (size_t)L;

    const int span = (L + bpd - 1) / bpd;
    const int s0   = c * span;
    int se = s0 + span; if (se > L) se = L;

    float s1a = 0.f, s1b = 0.f, s1c = 0.f, s1d = 0.f;
    float s2a = 0.f, s2b = 0.f, s2c = 0.f, s2d = 0.f;
    if (s0 < se) {
        // scalar head to 16B alignment
        uintptr_t addr = (uintptr_t)(base + s0);
        int mis = (int)(((16u - (unsigned)(addr & 15u)) & 15u) >> 2);
        int head_end = s0 + mis; if (head_end > se) head_end = se;
        for (int i = s0 + tid; i < head_end; i += RED_THREADS) {
            float v = base[i]; s1a += v; s2a = fmaf(v, v, s2a);
        }
        const int nvec = (se - head_end) >> 2;
        const float4* __restrict__ vbase = (const float4*)(base + head_end);

        int i = tid;
        // 8 independent LDG.128 per iteration (32 data regs) -> deep MLP
        for (; i + 7 * RED_THREADS < nvec; i += 8 * RED_THREADS) {
            float4 v0 = __ldcs(vbase + i);
            float4 v1 = __ldcs(vbase + i +     RED_THREADS);
            float4 v2 = __ldcs(vbase + i + 2 * RED_THREADS);
            float4 v3 = __ldcs(vbase + i + 3 * RED_THREADS);
            float4 v4 = __ldcs(vbase + i + 4 * RED_THREADS);
            float4 v5 = __ldcs(vbase + i + 5 * RED_THREADS);
            float4 v6 = __ldcs(vbase + i + 6 * RED_THREADS);
            float4 v7 = __ldcs(vbase + i + 7 * RED_THREADS);
            s1a += (v0.x + v0.y) + (v0.z + v0.w);
            s1b += (v1.x + v1.y) + (v1.z + v1.w);
            s1c += (v2.x + v2.y) + (v2.z + v2.w);
            s1d += (v3.x + v3.y) + (v3.z + v3.w);
            s1a += (v4.x + v4.y) + (v4.z + v4.w);
            s1b += (v5.x + v5.y) + (v5.z + v5.w);
            s1c += (v6.x + v6.y) + (v6.z + v6.w);
            s1d += (v7.x + v7.y) + (v7.z + v7.w);
            s2a += (v0.x * v0.x + v0.y * v0.y) + (v0.z * v0.z + v0.w * v0.w);
            s2b += (v1.x * v1.x + v1.y * v1.y) + (v1.z * v1.z + v1.w * v1.w);
            s2c += (v2.x * v2.x + v2.y * v2.y) + (v2.z * v2.z + v2.w * v2.w);
            s2d += (v3.x * v3.x + v3.y * v3.y) + (v3.z * v3.z + v3.w * v3.w);
            s2a += (v4.x * v4.x + v4.y * v4.y) + (v4.z * v4.z + v4.w * v4.w);
            s2b += (v5.x * v5.x + v5.y * v5.y) + (v5.z * v5.z + v5.w * v5.w);
            s2c += (v6.x * v6.x + v6.y * v6.y) + (v6.z * v6.z + v6.w * v6.w);
            s2d += (v7.x * v7.x + v7.y * v7.y) + (v7.z * v7.z + v7.w * v7.w);
        }
        for (; i < nvec; i += RED_THREADS) {
            float4 v = __ldcs(vbase + i);
            s1a += (v.x + v.y) + (v.z + v.w);
            s2a += (v.x * v.x + v.y * v.y) + (v.z * v.z + v.w * v.w);
        }
        for (int t = head_end + (nvec << 2) + tid; t < se; t += RED_THREADS) {
            float v = base[t]; s1a += v; s2a = fmaf(v, v, s2a);
        }
    }
    float s1 = (s1a + s1b) + (s1c + s1d);
    float s2 = (s2a + s2b) + (s2c + s2d);

    #pragma unroll
    for (int o = 16; o > 0; o >>= 1) {
        s1 += __shfl_down_sync(0xffffffffu, s1, o);
        s2 += __shfl_down_sync(0xffffffffu, s2, o);
    }
    __shared__ float sh1[RED_THREADS / 32], sh2[RED_THREADS / 32];
    if ((tid & 31) == 0) { sh1[tid >> 5] = s1; sh2[tid >> 5] = s2; }
    __syncthreads();
    if (tid == 0) {
        float t1 = 0.f, t2 = 0.f;
        #pragma unroll
        for (int w = 0; w < RED_THREADS / 32; ++w) { t1 += sh1[w]; t2 += sh2[w]; }
        g_part_sum[d][c] = t1;
        g_part_sq [d][c] = t2;
    }
}

// ---------------------------------------------------------------------------
// Kernel 2: FUSED finalize + coeff + T. Block (x = chunk of S/2, y = row i),
// 256 threads. Redundant partial-reduce per block (L2-hot, cheap), then
// coeff row i in smem, then Tr[i] (and Ti[i] if withImag).
// coeff identity: cos(atan2(mj,mi))=mi/hyp, sin=mj/hyp, amp=sqrt(pi*pj).
// ---------------------------------------------------------------------------
__global__ __launch_bounds__(256)
void k_T(const float* __restrict__ embed, int D, int S,
         int bpd, float invL, int withImag) {
    const int i   = blockIdx.y;
    const int tid = threadIdx.x;

    __shared__ float sm[DMAX], sp[DMAX];
    __shared__ float scr[DMAX], sci[DMAX];

    for (int j = tid; j < D; j += 256) {
        float s1 = 0.f, s2 = 0.f;
        for (int c = 0; c < bpd; ++c) {
            s1 += g_part_sum[j][c];
            s2 += g_part_sq [j][c];
        }
        sm[j] = s1 * invL;
        sp[j] = s2;
    }
    __syncthreads();
    for (int j = tid; j < D; j += 256) {
        float cr = 0.f, ci = 0.f;
        if (j > i) {
            const float mi = sm[i], mj = sm[j];
            const float amp = sqrtf(sp[i] * sp[j]);
            const float inv = rsqrtf(mi * mi + mj * mj);
            cr = amp * mi * inv;
            ci = amp * mj * inv;
        }
        scr[j] = cr;
        sci[j] = ci;
    }
    __syncthreads();
    if (withImag) {           // persist coeff for the complex fallback path
        for (int j = tid; j < D; j += 256) {
            g_cr[i][j] = scr[j];
            g_ci[i][j] = sci[j];
        }
    }

    const int halfS = S >> 1;
    const int s2i = blockIdx.x * 256 + tid;
    if (s2i < halfS) {
        const float2* __restrict__ e2 = (const float2*)embed;
        float2 ar = make_float2(0.f, 0.f);
        float2 ai = make_float2(0.f, 0.f);
        #pragma unroll 4
        for (int j = i + 1; j < D; ++j) {
            const float2 e = e2[(size_t)j * halfS + s2i];
            const float c = scr[j];
            ar.x = fmaf(c, e.x, ar.x);
            ar.y = fmaf(c, e.y, ar.y);
            if (withImag) {
                const float ic = sci[j];
                ai.x = fmaf(ic, e.x, ai.x);
                ai.y = fmaf(ic, e.y, ai.y);
            }
        }
        ((float2*)g_Tr[i])[s2i] = ar;
        if (withImag) ((float2*)g_Ti[i])[s2i] = ai;
    }
    // odd-S scalar tail
    if ((S & 1) && blockIdx.x == 0 && tid == 0) {
        const int s = S - 1;
        float ar = 0.f, ai = 0.f;
        for (int j = i + 1; j < D; ++j) {
            ar = fmaf(scr[j], embed[(size_t)j * S + s], ar);
            ai = fmaf(sci[j], embed[(size_t)j * S + s], ai);
        }
        g_Tr[i][s] = ar;
        if (withImag) g_Ti[i][s] = ai;
    }
}

// ---------------------------------------------------------------------------
// Kernel 3 (fast path, S%4==0): out = E^T @ Tr, REAL output.
// 32(a) x 64(b) tiles; K chunked by KC=64 into smem; 2x4 register blocking;
// float4 global+smem I/O.
// ---------------------------------------------------------------------------
__global__ __launch_bounds__(256)
void k_out_fast(const float* __restrict__ embed, float* __restrict__ out,
                int D, int S) {
    const int tid = threadIdx.x;
    const int tb  = tid & 15;          // b-group 0..15 (4 cols each)
    const int ta  = tid >> 4;          // a 0..15 (2 rows: ta, ta+16)
    const int b0  = blockIdx.x * 64;
    const int a0  = blockIdx.y * 32;

    __shared__ float Es [KC][32];
    __shared__ float Trs[KC][64];

    float a00 = 0.f, a01 = 0.f, a02 = 0.f, a03 = 0.f;
    float a10 = 0.f, a11 = 0.f, a12 = 0.f, a13 = 0.f;

    for (int k0 = 0; k0 < D; k0 += KC) {
        #pragma unroll
        for (int u = 0; u < 2; ++u) {
            const int e = tid + u * 256;
            const int kk = e >> 3, cc = (e & 7) << 2;
            const int k = k0 + kk;
            float4 v = make_float4(0.f, 0.f, 0.f, 0.f);
            if (k < D && a0 + cc + 3 < S)
                v = *(const float4*)&embed[(size_t)k * S + a0 + cc];
            *(float4*)&Es[kk][cc] = v;
        }
        #pragma unroll
        for (int u = 0; u < 4; ++u) {
            const int e = tid + u * 256;
            const int kk = e >> 4, cc = (e & 15) << 2;
            const int k = k0 + kk;
            float4 v = make_float4(0.f, 0.f, 0.f, 0.f);
            if (k < D && b0 + cc + 3 < S)
                v = *(const float4*)&g_Tr[k][b0 + cc];
            *(float4*)&Trs[kk][cc] = v;
        }
        __syncthreads();
        #pragma unroll 8
        for (int kk = 0; kk < KC; ++kk) {
            const float e0 = Es[kk][ta];
            const float e1 = Es[kk][ta + 16];
            const float4 t = *(const float4*)&Trs[kk][tb << 2];
            a00 = fmaf(e0, t.x, a00); a01 = fmaf(e0, t.y, a01);
            a02 = fmaf(e0, t.z, a02); a03 = fmaf(e0, t.w, a03);
            a10 = fmaf(e1, t.x, a10); a11 = fmaf(e1, t.y, a11);
            a12 = fmaf(e1, t.z, a12); a13 = fmaf(e1, t.w, a13);
        }
        __syncthreads();
    }
    const int b = b0 + (tb << 2);
    const int aA = a0 + ta, aB = a0 + ta + 16;
    if (aA < S && b + 3 < S)
        *(float4*)&out[(size_t)aA * S + b] = make_float4(a00, a01, a02, a03);
    if (aB < S && b + 3 < S)
        *(float4*)&out[(size_t)aB * S + b] = make_float4(a10, a11, a12, a13);
}

// ---------------------------------------------------------------------------
// Kernel 3 (generic real fallback, any S): 16x16 tiles.
// ---------------------------------------------------------------------------
__global__ __launch_bounds__(256)
void k_out_gen(const float* __restrict__ embed, float* __restrict__ out,
               int D, int S) {
    const int tx = threadIdx.x, ty = threadIdx.y;
    const int b0 = blockIdx.x * 16, a0 = blockIdx.y * 16;
    __shared__ float Es[16][17], Trs[16][17];
    float ar = 0.f;
    for (int k0 = 0; k0 < D; k0 += 16) {
        const int k = k0 + ty;
        const bool kv = (k < D);
        Es [ty][tx] = (kv && a0 + tx < S) ? embed[(size_t)k * S + a0 + tx] : 0.f;
        Trs[ty][tx] = (kv && b0 + tx < S) ? g_Tr[k][b0 + tx] : 0.f;
        __syncthreads();
        #pragma unroll
        for (int kk = 0; kk < 16; ++kk)
            ar = fmaf(Es[kk][ty], Trs[kk][tx], ar);
        __syncthreads();
    }
    const int a = a0 + ty, b = b0 + tx;
    if (a < S && b < S) out[(size_t)a * S + b] = ar;
}

// ---------------------------------------------------------------------------
// Kernel 3b: interleaved complex64 output (mode-1 fallback).
// ---------------------------------------------------------------------------
__global__ __launch_bounds__(256)
void k_out_cplx(const float* __restrict__ embed, float2* __restrict__ out,
                int D, int S) {
    const int tx = threadIdx.x, ty = threadIdx.y;
    const int b0 = blockIdx.x * 16, a0 = blockIdx.y * 16;
    __shared__ float Es[16][17], Trs[16][17], Tis[16][17];
    float ar = 0.f, ai = 0.f;
    for (int k0 = 0; k0 < D; k0 += 16) {
        const int k = k0 + ty;
        const bool kv = (k < D);
        Es [ty][tx] = (kv && a0 + tx < S) ? embed[(size_t)k * S + a0 + tx] : 0.f;
        Trs[ty][tx] = (kv && b0 + tx < S) ? g_Tr[k][b0 + tx] : 0.f;
        Tis[ty][tx] = (kv && b0 + tx < S) ? g_Ti[k][b0 + tx] : 0.f;
        __syncthreads();
        #pragma unroll
        for (int kk = 0; kk < 16; ++kk) {
            const float e = Es[kk][ty];
            ar = fmaf(e, Trs[kk][tx], ar);
            ai = fmaf(e, Tis[kk][tx], ai);
        }
        __syncthreads();
    }
    const int a = a0 + ty, b = b0 + tx;
    if (a < S && b < S) out[(size_t)a * S + b] = make_float2(ar, ai);
}

// ---------------------------------------------------------------------------
static long long isqrt_exact(long long x) {
    if (x <= 0) return -1;
    long long r = (long long)llround(sqrt((double)x));
    for (long long c = r - 2; c <= r + 2; ++c)
        if (c > 0 && c * c == x) return c;
    return -1;
}

extern "C" void kernel_launch(void* const* d_in, const int* in_sizes, int n_in,
                              void* d_out, int out_size) {
    if (n_in < 2) return;

    // Decode output mode + S:
    //  out_size == S*S    -> float32 real-part output (confirmed)
    //  out_size == 2*S*S  -> interleaved complex64 fallback
    int mode = 0;
    long long S_ll = isqrt_exact((long long)out_size);
    if (S_ll < 0 && (out_size % 2) == 0) {
        S_ll = isqrt_exact((long long)out_size / 2);
        mode = 1;
    }
    if (S_ll < 1) S_ll = 1;
    int S = (int)S_ll;
    if (S > SMAX) S = SMAX;

    // Identify inputs by size: embed is the smaller tensor [D,S], vulns [D,L].
    long long sz0 = in_sizes[0], sz1 = in_sizes[1];
    const float* vulns; const float* embed;
    long long vsz, esz;
    if (sz0 >= sz1) { vulns = (const float*)d_in[0]; vsz = sz0;
                      embed = (const float*)d_in[1]; esz = sz1; }
    else            { vulns = (const float*)d_in[1]; vsz = sz1;
                      embed = (const float*)d_in[0]; esz = sz0; }

    int D = (int)(esz / S);
    if (D < 1) D = 1;
    if (D > DMAX) D = DMAX;
    long long L_ll = vsz / D;
    if (L_ll < 1) L_ll = 1;
    int L = (int)L_ll;

    int bpd = (1024 + D - 1) / D;      // ~1024 CTAs total
    if (bpd < 1) bpd = 1;
    if (bpd > BPDMAX) bpd = BPDMAX;

    k_reduce<<<dim3(bpd, D), RED_THREADS>>>(vulns, L, bpd);

    const int halfS = S >> 1;
    int tchunks = (halfS + 255) / 256; if (tchunks < 1) tchunks = 1;
    k_T<<<dim3(tchunks, D), 256>>>(embed, D, S, bpd, 1.0f / (float)L, mode);

    if (mode == 0) {
        bool fast = ((S & 3) == 0) && (((uintptr_t)embed & 15u) == 0) &&
                    (((uintptr_t)d_out & 15u) == 0);
        if (fast) {
            k_out_fast<<<dim3((S + 63) / 64, (S + 31) / 32), 256>>>(
                embed, (float*)d_out, D, S);
        } else {
            k_out_gen<<<dim3((S + 15) / 16, (S + 15) / 16), dim3(16, 16)>>>(
                embed, (float*)d_out, D, S);
        }
    } else {
        k_out_cplx<<<dim3((S + 15) / 16, (S + 15) / 16), dim3(16, 16)>>>(
            embed, (float2*)d_out, D, S);
    }
}